// round 7
// baseline (speedup 1.0000x reference)
#include <cuda_runtime.h>

constexpr int NMAX  = 100000;
constexpr int D_IN  = 16;
constexpr int D_HID = 32;
constexpr int D_OUT = 16;

// Scratch (__device__ globals; allocation-free rule). Zero-initialized at load.
__device__ alignas(16) float g_pre [NMAX * D_IN];   // emb[x[v]] * dinv[v]
__device__ alignas(16) float g_agg1[NMAX * D_IN];   // self + Sum over in-edges
__device__ alignas(16) float g_hs2 [NMAX * D_OUT];  // (relu(conv1)@W2) * dinv
__device__ alignas(16) float g_agg2[NMAX * D_OUT];  // self + Sum over in-edges
__device__ float g_dinv[NMAX];
__device__ int   g_deg [NMAX];   // 0 at entry (static init / reset by k_pre)

// ---------------------------------------------------------------------------
// K1: degree histogram over real edges (self-loop folded as +1 in k_pre).
__global__ void k_deg(const int* __restrict__ dst, int E) {
    int i = blockIdx.x * blockDim.x + threadIdx.x;
    int e4 = i * 4;
    if (e4 + 3 < E) {
        int4 d = *reinterpret_cast<const int4*>(dst + e4);
        atomicAdd(&g_deg[d.x], 1); atomicAdd(&g_deg[d.y], 1);
        atomicAdd(&g_deg[d.z], 1); atomicAdd(&g_deg[d.w], 1);
    } else {
        for (int e = e4; e < E && e >= 0; e++) atomicAdd(&g_deg[dst[e]], 1);
    }
}

// K2: 4 threads per node (one float4 chunk each): dinv; pre = emb[x[v]]*dinv;
//     agg1 = pre (self-loop seed); reset deg. Node's 4 threads share a warp
//     and are convergent at the load, so read-before-lane0-reset is race-free.
__global__ void k_pre(const int* __restrict__ x, const float* __restrict__ emb,
                      int n) {
    int t = blockIdx.x * blockDim.x + threadIdx.x;
    int v = t >> 2, q = t & 3;
    if (v >= n) return;
    int d = g_deg[v];
    float dinv = rsqrtf((float)(d + 1));
    if (q == 0) { g_deg[v] = 0; g_dinv[v] = dinv; }
    int xr = __ldg(&x[v]);
    float4 e = reinterpret_cast<const float4*>(emb)[(size_t)xr * 4 + q];
    float4 p = make_float4(e.x * dinv, e.y * dinv, e.z * dinv, e.w * dinv);
    reinterpret_cast<float4*>(g_pre )[(size_t)v * 4 + q] = p;
    reinterpret_cast<float4*>(g_agg1)[(size_t)v * 4 + q] = p;
}

// K3/K5: edge scatter in 16-dim space: 4 threads per edge, red.v4 per thread.
template <int LAYER>
__global__ void k_scatter(const int* __restrict__ src, const int* __restrict__ dst,
                          int E) {
    const float* in  = (LAYER == 1) ? g_pre  : g_hs2;
    float*       out = (LAYER == 1) ? g_agg1 : g_agg2;

    long long t = (long long)blockIdx.x * blockDim.x + threadIdx.x;
    int e = (int)(t >> 2);
    if (e >= E) return;
    int c = (int)t & 3;

    int s = __ldg(&src[e]);
    int d = __ldg(&dst[e]);

    float4 v = *reinterpret_cast<const float4*>(in + ((size_t)s << 4) + c * 4);
    float* p = out + ((size_t)d << 4) + c * 4;
    asm volatile("red.global.add.v4.f32 [%0], {%1,%2,%3,%4};"
                 :: "l"(p), "f"(v.x), "f"(v.y), "f"(v.z), "f"(v.w) : "memory");
}

// K4: 4 threads per node. Lane q owns W1 columns [8q,8q+8) and W2 rows
//     [8q,8q+8). a gathered via width-4 shuffles; h combined via branch-free
//     reduce-scatter (2 rounds). Seeds agg2 = hs2 = dinv*(relu(a@W1+b1)@W2).
__global__ void k_mid(const float* __restrict__ W1, const float* __restrict__ b1,
                      const float* __restrict__ W2, int n) {
    __shared__ float W1s[D_IN * D_HID];
    __shared__ float W2s[D_HID * D_OUT];
    __shared__ float b1s[D_HID];
    for (int t = threadIdx.x; t < D_IN * D_HID; t += blockDim.x) W1s[t] = W1[t];
    for (int t = threadIdx.x; t < D_HID * D_OUT; t += blockDim.x) W2s[t] = W2[t];
    if (threadIdx.x < D_HID) b1s[threadIdx.x] = b1[threadIdx.x];
    __syncthreads();

    int t = blockIdx.x * blockDim.x + threadIdx.x;
    int v = t >> 2, q = t & 3;
    if (v >= n) return;

    float dinv = g_dinv[v];
    float4 av = reinterpret_cast<const float4*>(g_agg1)[(size_t)v * 4 + q];
    float al[4] = {av.x * dinv, av.y * dinv, av.z * dinv, av.w * dinv};

    // Gather full a[16] across the 4-lane group (16 width-4 shuffles).
    float a[D_IN];
#pragma unroll
    for (int c = 0; c < 4; c++) {
#pragma unroll
        for (int i = 0; i < 4; i++)
            a[c * 4 + i] = __shfl_sync(~0u, al[i], c, 4);
    }

    // r[t] = relu(b1 + a @ W1[:, 8q+t]), t = 0..7.  (128 FMA)
    int j0 = q * 8;
    float r[8];
#pragma unroll
    for (int tt = 0; tt < 8; tt++) r[tt] = b1s[j0 + tt];
#pragma unroll
    for (int k = 0; k < D_IN; k++) {
        float ak = a[k];
#pragma unroll
        for (int tt = 0; tt < 8; tt++)
            r[tt] = fmaf(ak, W1s[k * D_HID + j0 + tt], r[tt]);
    }
#pragma unroll
    for (int tt = 0; tt < 8; tt++) r[tt] = fmaxf(r[tt], 0.f);

    // Partial h[16] from this lane's 8 W2 rows.  (128 FMA)
    float ph[D_OUT];
#pragma unroll
    for (int j = 0; j < D_OUT; j++) ph[j] = 0.f;
#pragma unroll
    for (int tt = 0; tt < 8; tt++) {
        float rv = r[tt];
#pragma unroll
        for (int j = 0; j < D_OUT; j++)
            ph[j] = fmaf(rv, W2s[(j0 + tt) * D_OUT + j], ph[j]);
    }

    // Reduce-scatter round 1 (xor 1): keep 8 values (lo half if q&1==0).
    bool hiA = (q & 1);
    float k8[8];
#pragma unroll
    for (int i = 0; i < 8; i++) {
        float lo = ph[i], hi = ph[8 + i];
        float send = hiA ? lo : hi;
        float recv = __shfl_xor_sync(~0u, send, 1, 4);
        k8[i] = (hiA ? hi : lo) + recv;
    }
    // Round 2 (xor 2): keep 4.
    bool hiB = (q & 2);
    float h[4];
#pragma unroll
    for (int i = 0; i < 4; i++) {
        float lo = k8[i], hi = k8[4 + i];
        float send = hiB ? lo : hi;
        float recv = __shfl_xor_sync(~0u, send, 2, 4);
        h[i] = (hiB ? hi : lo) + recv;
    }
    // Lane q holds h[base .. base+4), base = ((q&1)<<3) | ((q&2)<<1).
    int base = ((q & 1) << 3) | ((q & 2) << 1);
    float4 hv = make_float4(h[0] * dinv, h[1] * dinv, h[2] * dinv, h[3] * dinv);
    *reinterpret_cast<float4*>(g_hs2  + (size_t)v * D_OUT + base) = hv;
    *reinterpret_cast<float4*>(g_agg2 + (size_t)v * D_OUT + base) = hv;
}

// K6: 4 threads per node: out = agg2*dinv + b2.
__global__ void k_post(const float* __restrict__ b2, float* __restrict__ out, int n) {
    int t = blockIdx.x * blockDim.x + threadIdx.x;
    int v = t >> 2, q = t & 3;
    if (v >= n) return;
    float dinv = g_dinv[v];
    float4 a = reinterpret_cast<const float4*>(g_agg2)[(size_t)v * 4 + q];
    float4 bb = __ldg(reinterpret_cast<const float4*>(b2) + q);
    reinterpret_cast<float4*>(out)[(size_t)v * 4 + q] =
        make_float4(dinv * a.x + bb.x, dinv * a.y + bb.y,
                    dinv * a.z + bb.z, dinv * a.w + bb.w);
}

extern "C" void kernel_launch(void* const* d_in, const int* in_sizes, int n_in,
                              void* d_out, int out_size) {
    const int*   x   = (const int*)  d_in[0];
    const int*   ei  = (const int*)  d_in[1];   // [2, E]: src then dst
    const float* emb = (const float*)d_in[2];
    const float* W1  = (const float*)d_in[3];
    const float* b1  = (const float*)d_in[4];
    const float* W2  = (const float*)d_in[5];
    const float* b2  = (const float*)d_in[6];
    float* out = (float*)d_out;

    int n = in_sizes[0];
    int E = in_sizes[1] / 2;
    const int* src = ei;
    const int* dst = ei + E;

    const int B = 256;
    long long et = (long long)E * 4;
    int nb_edge  = (int)((et + B - 1) / B);
    int nb_node4 = (n * 4 + B - 1) / B;

    k_deg       <<<(E / 4 + B - 1) / B + 1, B>>>(dst, E);
    k_pre       <<<nb_node4, B>>>(x, emb, n);
    k_scatter<1><<<nb_edge, B>>>(src, dst, E);
    k_mid       <<<nb_node4, B>>>(W1, b1, W2, n);
    k_scatter<2><<<nb_edge, B>>>(src, dst, E);
    k_post      <<<nb_node4, B>>>(b2, out, n);
}

// round 8
// speedup vs baseline: 1.8960x; 1.8960x over previous
#include <cuda_runtime.h>

constexpr int NMAX  = 100000;
constexpr int D_IN  = 16;
constexpr int D_HID = 32;
constexpr int D_OUT = 16;

// Scratch (__device__ globals; allocation-free rule). Zero-initialized at load.
__device__ alignas(16) float g_pre [NMAX * D_IN];   // emb[x[v]] * dinv[v]
__device__ alignas(16) float g_agg1[NMAX * D_IN];   // self + Sum over in-edges
__device__ alignas(16) float g_hs2 [NMAX * D_OUT];  // (relu(conv1)@W2) * dinv
__device__ alignas(16) float g_agg2[NMAX * D_OUT];  // self + Sum over in-edges
__device__ float g_dinv[NMAX];
__device__ int   g_deg [NMAX];   // 0 at entry (static init / reset by k_pre)

// ---------------------------------------------------------------------------
// K1: degree histogram over real edges (self-loop folded as +1 in k_pre).
__global__ void k_deg(const int* __restrict__ dst, int E) {
    int i = blockIdx.x * blockDim.x + threadIdx.x;
    int e4 = i * 4;
    if (e4 + 3 < E) {
        int4 d = *reinterpret_cast<const int4*>(dst + e4);
        atomicAdd(&g_deg[d.x], 1); atomicAdd(&g_deg[d.y], 1);
        atomicAdd(&g_deg[d.z], 1); atomicAdd(&g_deg[d.w], 1);
    } else {
        for (int e = e4; e < E && e >= 0; e++) atomicAdd(&g_deg[dst[e]], 1);
    }
}

// K2: 4 threads per node (one float4 chunk each): dinv; pre = emb[x[v]]*dinv;
//     agg1 = pre (self-loop seed); reset deg. Node's 4 threads share a warp
//     and are convergent at the load, so read-before-lane0-reset is race-free.
__global__ void k_pre(const int* __restrict__ x, const float* __restrict__ emb,
                      int n) {
    int t = blockIdx.x * blockDim.x + threadIdx.x;
    int v = t >> 2, q = t & 3;
    if (v >= n) return;
    int d = g_deg[v];
    float dinv = rsqrtf((float)(d + 1));
    if (q == 0) { g_deg[v] = 0; g_dinv[v] = dinv; }
    int xr = __ldg(&x[v]);
    float4 e = reinterpret_cast<const float4*>(emb)[(size_t)xr * 4 + q];
    float4 p = make_float4(e.x * dinv, e.y * dinv, e.z * dinv, e.w * dinv);
    reinterpret_cast<float4*>(g_pre )[(size_t)v * 4 + q] = p;
    reinterpret_cast<float4*>(g_agg1)[(size_t)v * 4 + q] = p;
}

// K3/K5: edge scatter in 16-dim space: 4 threads per edge, red.v4 per thread.
template <int LAYER>
__global__ void k_scatter(const int* __restrict__ src, const int* __restrict__ dst,
                          int E) {
    const float* in  = (LAYER == 1) ? g_pre  : g_hs2;
    float*       out = (LAYER == 1) ? g_agg1 : g_agg2;

    long long t = (long long)blockIdx.x * blockDim.x + threadIdx.x;
    int e = (int)(t >> 2);
    if (e >= E) return;
    int c = (int)t & 3;

    int s = __ldg(&src[e]);
    int d = __ldg(&dst[e]);

    float4 v = *reinterpret_cast<const float4*>(in + ((size_t)s << 4) + c * 4);
    float* p = out + ((size_t)d << 4) + c * 4;
    asm volatile("red.global.add.v4.f32 [%0], {%1,%2,%3,%4};"
                 :: "l"(p), "f"(v.x), "f"(v.y), "f"(v.z), "f"(v.w) : "memory");
}

// K4: thread per node (R4 structure), but ALL weight reads are float4 LDS
//     (warp-uniform -> broadcast, conflict-free): 256 LDS.128 + 1024 FMA per
//     thread. a = agg1*dinv; r = relu(a@W1+b1); hs2 = agg2 = (r@W2)*dinv.
__global__ void k_mid(const float* __restrict__ W1, const float* __restrict__ b1,
                      const float* __restrict__ W2, int n) {
    __shared__ float4 W1s[D_IN * (D_HID / 4)];   // 16 x 8 float4
    __shared__ float4 W2s[D_HID * (D_OUT / 4)];  // 32 x 4 float4
    __shared__ float4 b1s[D_HID / 4];
    for (int t = threadIdx.x; t < D_IN * D_HID / 4; t += blockDim.x)
        W1s[t] = reinterpret_cast<const float4*>(W1)[t];
    for (int t = threadIdx.x; t < D_HID * D_OUT / 4; t += blockDim.x)
        W2s[t] = reinterpret_cast<const float4*>(W2)[t];
    if (threadIdx.x < D_HID / 4)
        b1s[threadIdx.x] = reinterpret_cast<const float4*>(b1)[threadIdx.x];
    __syncthreads();

    int v = blockIdx.x * blockDim.x + threadIdx.x;
    if (v >= n) return;

    float dinv = g_dinv[v];
    float a[D_IN];
    const float4* ar = reinterpret_cast<const float4*>(g_agg1 + (size_t)v * D_IN);
#pragma unroll
    for (int q = 0; q < D_IN / 4; q++) {
        float4 t = ar[q];
        a[q*4+0] = t.x * dinv; a[q*4+1] = t.y * dinv;
        a[q*4+2] = t.z * dinv; a[q*4+3] = t.w * dinv;
    }

    float r[D_HID];
#pragma unroll
    for (int j = 0; j < D_HID / 4; j++) {
        float4 b = b1s[j];
        r[j*4+0] = b.x; r[j*4+1] = b.y; r[j*4+2] = b.z; r[j*4+3] = b.w;
    }
#pragma unroll
    for (int k = 0; k < D_IN; k++) {
        float ak = a[k];
#pragma unroll
        for (int j = 0; j < D_HID / 4; j++) {
            float4 w = W1s[k * (D_HID / 4) + j];
            r[j*4+0] = fmaf(ak, w.x, r[j*4+0]);
            r[j*4+1] = fmaf(ak, w.y, r[j*4+1]);
            r[j*4+2] = fmaf(ak, w.z, r[j*4+2]);
            r[j*4+3] = fmaf(ak, w.w, r[j*4+3]);
        }
    }
#pragma unroll
    for (int j = 0; j < D_HID; j++) r[j] = fmaxf(r[j], 0.f);

    float h[D_OUT];
#pragma unroll
    for (int j = 0; j < D_OUT; j++) h[j] = 0.f;
#pragma unroll
    for (int k = 0; k < D_HID; k++) {
        float rv = r[k];
#pragma unroll
        for (int j = 0; j < D_OUT / 4; j++) {
            float4 w = W2s[k * (D_OUT / 4) + j];
            h[j*4+0] = fmaf(rv, w.x, h[j*4+0]);
            h[j*4+1] = fmaf(rv, w.y, h[j*4+1]);
            h[j*4+2] = fmaf(rv, w.z, h[j*4+2]);
            h[j*4+3] = fmaf(rv, w.w, h[j*4+3]);
        }
    }

    float4* hr = reinterpret_cast<float4*>(g_hs2  + (size_t)v * D_OUT);
    float4* gr = reinterpret_cast<float4*>(g_agg2 + (size_t)v * D_OUT);
#pragma unroll
    for (int q = 0; q < D_OUT / 4; q++) {
        float4 t = make_float4(h[q*4+0]*dinv, h[q*4+1]*dinv,
                               h[q*4+2]*dinv, h[q*4+3]*dinv);
        hr[q] = t;
        gr[q] = t;
    }
}

// K6: 4 threads per node: out = agg2*dinv + b2.
__global__ void k_post(const float* __restrict__ b2, float* __restrict__ out, int n) {
    int t = blockIdx.x * blockDim.x + threadIdx.x;
    int v = t >> 2, q = t & 3;
    if (v >= n) return;
    float dinv = g_dinv[v];
    float4 a = reinterpret_cast<const float4*>(g_agg2)[(size_t)v * 4 + q];
    float4 bb = __ldg(reinterpret_cast<const float4*>(b2) + q);
    reinterpret_cast<float4*>(out)[(size_t)v * 4 + q] =
        make_float4(dinv * a.x + bb.x, dinv * a.y + bb.y,
                    dinv * a.z + bb.z, dinv * a.w + bb.w);
}

extern "C" void kernel_launch(void* const* d_in, const int* in_sizes, int n_in,
                              void* d_out, int out_size) {
    const int*   x   = (const int*)  d_in[0];
    const int*   ei  = (const int*)  d_in[1];   // [2, E]: src then dst
    const float* emb = (const float*)d_in[2];
    const float* W1  = (const float*)d_in[3];
    const float* b1  = (const float*)d_in[4];
    const float* W2  = (const float*)d_in[5];
    const float* b2  = (const float*)d_in[6];
    float* out = (float*)d_out;

    int n = in_sizes[0];
    int E = in_sizes[1] / 2;
    const int* src = ei;
    const int* dst = ei + E;

    const int B = 256;
    long long et = (long long)E * 4;
    int nb_edge  = (int)((et + B - 1) / B);
    int nb_node4 = (n * 4 + B - 1) / B;

    k_deg       <<<(E / 4 + B - 1) / B + 1, B>>>(dst, E);
    k_pre       <<<nb_node4, B>>>(x, emb, n);
    k_scatter<1><<<nb_edge, B>>>(src, dst, E);
    k_mid       <<<(n + 127) / 128, 128>>>(W1, b1, W2, n);
    k_scatter<2><<<nb_edge, B>>>(src, dst, E);
    k_post      <<<nb_node4, B>>>(b2, out, n);
}

// round 9
// speedup vs baseline: 1.9196x; 1.0124x over previous
#include <cuda_runtime.h>

constexpr int NMAX  = 100000;
constexpr int D_IN  = 16;
constexpr int D_HID = 32;
constexpr int D_OUT = 16;

// Scratch (__device__ globals; allocation-free rule). Zero-initialized at load.
__device__ alignas(16) float g_pre [NMAX * D_IN];   // emb[x[v]] * dinv[v]
__device__ alignas(16) float g_agg1[NMAX * D_IN];   // self + Sum over in-edges
__device__ alignas(16) float g_hs2 [NMAX * D_OUT];  // (relu(conv1)@W2) * dinv
__device__ alignas(16) float g_agg2[NMAX * D_OUT];  // self + Sum over in-edges
__device__ float g_dinv[NMAX];
__device__ int   g_deg [NMAX];   // 0 at entry (static init / reset by k_pre)

// ---------------------------------------------------------------------------
// K1: degree histogram over real edges (self-loop folded as +1 in k_pre).
__global__ void k_deg(const int* __restrict__ dst, int E) {
    int i = blockIdx.x * blockDim.x + threadIdx.x;
    int e4 = i * 4;
    if (e4 + 3 < E) {
        int4 d = *reinterpret_cast<const int4*>(dst + e4);
        atomicAdd(&g_deg[d.x], 1); atomicAdd(&g_deg[d.y], 1);
        atomicAdd(&g_deg[d.z], 1); atomicAdd(&g_deg[d.w], 1);
    } else {
        for (int e = e4; e < E && e >= 0; e++) atomicAdd(&g_deg[dst[e]], 1);
    }
}

// K2: 4 threads per node (one float4 chunk each): dinv; pre = emb[x[v]]*dinv;
//     agg1 = pre (self-loop seed); reset deg. Node's 4 threads share a warp
//     and are convergent at the load, so read-before-lane0-reset is race-free.
__global__ void k_pre(const int* __restrict__ x, const float* __restrict__ emb,
                      int n) {
    int t = blockIdx.x * blockDim.x + threadIdx.x;
    int v = t >> 2, q = t & 3;
    if (v >= n) return;
    int d = g_deg[v];
    float dinv = rsqrtf((float)(d + 1));
    if (q == 0) { g_deg[v] = 0; g_dinv[v] = dinv; }
    int xr = __ldg(&x[v]);
    float4 e = reinterpret_cast<const float4*>(emb)[(size_t)xr * 4 + q];
    float4 p = make_float4(e.x * dinv, e.y * dinv, e.z * dinv, e.w * dinv);
    reinterpret_cast<float4*>(g_pre )[(size_t)v * 4 + q] = p;
    reinterpret_cast<float4*>(g_agg1)[(size_t)v * 4 + q] = p;
}

// K3/K5: edge scatter in 16-dim space: 4 threads per edge, red.v4 per thread.
template <int LAYER>
__global__ void k_scatter(const int* __restrict__ src, const int* __restrict__ dst,
                          int E) {
    const float* in  = (LAYER == 1) ? g_pre  : g_hs2;
    float*       out = (LAYER == 1) ? g_agg1 : g_agg2;

    long long t = (long long)blockIdx.x * blockDim.x + threadIdx.x;
    int e = (int)(t >> 2);
    if (e >= E) return;
    int c = (int)t & 3;

    int s = __ldg(&src[e]);
    int d = __ldg(&dst[e]);

    float4 v = *reinterpret_cast<const float4*>(in + ((size_t)s << 4) + c * 4);
    float* p = out + ((size_t)d << 4) + c * 4;
    asm volatile("red.global.add.v4.f32 [%0], {%1,%2,%3,%4};"
                 :: "l"(p), "f"(v.x), "f"(v.y), "f"(v.z), "f"(v.w) : "memory");
}

// K4: TWO threads per node (pair = lanes xor 1). Lane p owns W1 columns
//     [16p,16p+16) and W2 rows [16p,16p+16). No redundant FMA; a[] gathered
//     with 8 parallel shfl_xor + SEL (compile-time reg indices, no spills);
//     h combined with 8 shuffles. All LDS are float4, 2 distinct addrs/warp.
__global__ void k_mid(const float* __restrict__ W1, const float* __restrict__ b1,
                      const float* __restrict__ W2, int n) {
    __shared__ float4 W1s[D_IN * (D_HID / 4)];   // [k][j4] 16 x 8
    __shared__ float4 W2s[D_HID * (D_OUT / 4)];  // [k][j4] 32 x 4
    __shared__ float4 b1s[D_HID / 4];
    for (int t = threadIdx.x; t < D_IN * D_HID / 4; t += blockDim.x)
        W1s[t] = reinterpret_cast<const float4*>(W1)[t];
    for (int t = threadIdx.x; t < D_HID * D_OUT / 4; t += blockDim.x)
        W2s[t] = reinterpret_cast<const float4*>(W2)[t];
    if (threadIdx.x < D_HID / 4)
        b1s[threadIdx.x] = reinterpret_cast<const float4*>(b1)[threadIdx.x];
    __syncthreads();

    int t = blockIdx.x * blockDim.x + threadIdx.x;
    int v = t >> 1, p = t & 1;
    if (v >= n) return;

    float dinv = g_dinv[v];
    const float4* ar = reinterpret_cast<const float4*>(g_agg1 + (size_t)v * D_IN);
    float4 a0 = ar[2 * p], a1 = ar[2 * p + 1];
    float al[8] = {a0.x * dinv, a0.y * dinv, a0.z * dinv, a0.w * dinv,
                   a1.x * dinv, a1.y * dinv, a1.z * dinv, a1.w * dinv};

    // Build full a[16]: lane p owns a[8p..8p+8); partner supplies the rest.
    float a[D_IN];
    bool hi = (p != 0);
#pragma unroll
    for (int i = 0; i < 8; i++) {
        float theirs = __shfl_xor_sync(~0u, al[i], 1);
        a[i]     = hi ? theirs : al[i];
        a[8 + i] = hi ? al[i] : theirs;
    }

    // r[16] = relu(b1 + a @ W1)[16p .. 16p+16).   (256 FMA, 64+4 LDS.128)
    int jb = 4 * p;                       // first float4-column of my half
    float r[16];
#pragma unroll
    for (int j4 = 0; j4 < 4; j4++) {
        float4 b = b1s[jb + j4];
        r[j4*4+0] = b.x; r[j4*4+1] = b.y; r[j4*4+2] = b.z; r[j4*4+3] = b.w;
    }
#pragma unroll
    for (int k = 0; k < D_IN; k++) {
        float ak = a[k];
#pragma unroll
        for (int j4 = 0; j4 < 4; j4++) {
            float4 w = W1s[k * (D_HID / 4) + jb + j4];
            r[j4*4+0] = fmaf(ak, w.x, r[j4*4+0]);
            r[j4*4+1] = fmaf(ak, w.y, r[j4*4+1]);
            r[j4*4+2] = fmaf(ak, w.z, r[j4*4+2]);
            r[j4*4+3] = fmaf(ak, w.w, r[j4*4+3]);
        }
    }
#pragma unroll
    for (int j = 0; j < 16; j++) r[j] = fmaxf(r[j], 0.f);

    // Partial h over my 16 W2 rows [16p .. 16p+16).  (256 FMA, 64 LDS.128)
    int kb = 16 * p;
    float ph[D_OUT];
#pragma unroll
    for (int j = 0; j < D_OUT; j++) ph[j] = 0.f;
#pragma unroll
    for (int kk = 0; kk < 16; kk++) {
        float rv = r[kk];
#pragma unroll
        for (int j4 = 0; j4 < 4; j4++) {
            float4 w = W2s[(kb + kk) * (D_OUT / 4) + j4];
            ph[j4*4+0] = fmaf(rv, w.x, ph[j4*4+0]);
            ph[j4*4+1] = fmaf(rv, w.y, ph[j4*4+1]);
            ph[j4*4+2] = fmaf(rv, w.z, ph[j4*4+2]);
            ph[j4*4+3] = fmaf(rv, w.w, ph[j4*4+3]);
        }
    }

    // Combine: lane p keeps final h[8p .. 8p+8), scaled by dinv.  (8 SHFL)
    float h[8];
#pragma unroll
    for (int i = 0; i < 8; i++) {
        float send = hi ? ph[i] : ph[8 + i];
        float recv = __shfl_xor_sync(~0u, send, 1);
        h[i] = ((hi ? ph[8 + i] : ph[i]) + recv) * dinv;
    }

    float4 h0 = make_float4(h[0], h[1], h[2], h[3]);
    float4 h1 = make_float4(h[4], h[5], h[6], h[7]);
    size_t off = (size_t)v * D_OUT + 8 * p;
    *reinterpret_cast<float4*>(g_hs2  + off)     = h0;
    *reinterpret_cast<float4*>(g_hs2  + off + 4) = h1;
    *reinterpret_cast<float4*>(g_agg2 + off)     = h0;
    *reinterpret_cast<float4*>(g_agg2 + off + 4) = h1;
}

// K6: 4 threads per node: out = agg2*dinv + b2.
__global__ void k_post(const float* __restrict__ b2, float* __restrict__ out, int n) {
    int t = blockIdx.x * blockDim.x + threadIdx.x;
    int v = t >> 2, q = t & 3;
    if (v >= n) return;
    float dinv = g_dinv[v];
    float4 a = reinterpret_cast<const float4*>(g_agg2)[(size_t)v * 4 + q];
    float4 bb = __ldg(reinterpret_cast<const float4*>(b2) + q);
    reinterpret_cast<float4*>(out)[(size_t)v * 4 + q] =
        make_float4(dinv * a.x + bb.x, dinv * a.y + bb.y,
                    dinv * a.z + bb.z, dinv * a.w + bb.w);
}

extern "C" void kernel_launch(void* const* d_in, const int* in_sizes, int n_in,
                              void* d_out, int out_size) {
    const int*   x   = (const int*)  d_in[0];
    const int*   ei  = (const int*)  d_in[1];   // [2, E]: src then dst
    const float* emb = (const float*)d_in[2];
    const float* W1  = (const float*)d_in[3];
    const float* b1  = (const float*)d_in[4];
    const float* W2  = (const float*)d_in[5];
    const float* b2  = (const float*)d_in[6];
    float* out = (float*)d_out;

    int n = in_sizes[0];
    int E = in_sizes[1] / 2;
    const int* src = ei;
    const int* dst = ei + E;

    const int B = 256;
    long long et = (long long)E * 4;
    int nb_edge  = (int)((et + B - 1) / B);
    int nb_node4 = (n * 4 + B - 1) / B;
    int nb_node2 = (n * 2 + B - 1) / B;

    k_deg       <<<(E / 4 + B - 1) / B + 1, B>>>(dst, E);
    k_pre       <<<nb_node4, B>>>(x, emb, n);
    k_scatter<1><<<nb_edge, B>>>(src, dst, E);
    k_mid       <<<nb_node2, B>>>(W1, b1, W2, n);
    k_scatter<2><<<nb_edge, B>>>(src, dst, E);
    k_post      <<<nb_node4, B>>>(b2, out, n);
}